// round 2
// baseline (speedup 1.0000x reference)
#include <cuda_runtime.h>
#include <cstdint>

#define SEQ  4096
#define EMBD 200
#define HID  256
#define G3   768   // 3*HID

// Scratch for precomputed input-gate projections, permuted per (dir, t, rank):
// layout: gi[dir*SEQ*G3 + s*G3 + rank*192 + gate*64 + j]
__device__ float g_gi[2u * SEQ * G3];

typedef unsigned long long ull;

__device__ __forceinline__ ull fma2(ull a, ull b, ull c) {
    ull d;
    asm("fma.rn.f32x2 %0, %1, %2, %3;" : "=l"(d) : "l"(a), "l"(b), "l"(c));
    return d;
}
__device__ __forceinline__ unsigned s2u(const void* p) {
    return (unsigned)__cvta_generic_to_shared(p);
}
__device__ __forceinline__ float sigm(float x) { return 1.0f / (1.0f + __expf(-x)); }
__device__ __forceinline__ float tanhx(float x) {
    float e = __expf(2.0f * x);
    return 1.0f - 2.0f / (e + 1.0f);   // safe for +/- saturation
}

// ---------------------------------------------------------------------------
// Kernel A: embedding gather -> d_out[0 .. SEQ*EMBD)
// ---------------------------------------------------------------------------
__global__ void embed_kernel(const int* __restrict__ utt,
                             const float* __restrict__ embw,
                             float* __restrict__ out) {
    int i = blockIdx.x * blockDim.x + threadIdx.x;
    if (i < SEQ * EMBD) {
        int t = i / EMBD;
        int k = i - t * EMBD;
        out[i] = __ldg(&embw[(size_t)utt[t] * EMBD + k]);
    }
}

// ---------------------------------------------------------------------------
// Kernel B: gi = X @ W_ih^T + b_ih for both directions, written permuted.
// Grid (64, 12, 2): 64x64 output tiles (t x rows), block 256 threads, 4x4 micro.
// ---------------------------------------------------------------------------
__global__ void __launch_bounds__(256, 1)
gi_gemm(const float* __restrict__ X,
        const float* __restrict__ wih1, const float* __restrict__ bih1,
        const float* __restrict__ wih2, const float* __restrict__ bih2) {
    const int dir = blockIdx.z;
    const float* W = dir ? wih2 : wih1;
    const float* B = dir ? bih2 : bih1;
    const int t0 = blockIdx.x * 64;
    const int r0 = blockIdx.y * 64;

    __shared__ float xs[8][65];
    __shared__ float ws[8][65];

    const int tid = threadIdx.x;
    const int tx = tid & 15;      // t dimension
    const int ty = tid >> 4;      // row dimension

    float acc[4][4];
#pragma unroll
    for (int i = 0; i < 4; i++)
#pragma unroll
        for (int k = 0; k < 4; k++) acc[i][k] = 0.0f;

    for (int k0 = 0; k0 < EMBD; k0 += 8) {
#pragma unroll
        for (int i = 0; i < 2; i++) {
            int f = tid + i * 256;
            int kk = f & 7, tt = f >> 3;
            xs[kk][tt] = X[(size_t)(t0 + tt) * EMBD + k0 + kk];
        }
#pragma unroll
        for (int i = 0; i < 2; i++) {
            int f = tid + i * 256;
            int kk = f & 7, rr = f >> 3;
            ws[kk][rr] = W[(size_t)(r0 + rr) * EMBD + k0 + kk];
        }
        __syncthreads();
#pragma unroll
        for (int kk = 0; kk < 8; kk++) {
            float a[4], b[4];
#pragma unroll
            for (int i = 0; i < 4; i++) { a[i] = xs[kk][tx * 4 + i]; b[i] = ws[kk][ty * 4 + i]; }
#pragma unroll
            for (int ri = 0; ri < 4; ri++)
#pragma unroll
                for (int ti = 0; ti < 4; ti++)
                    acc[ri][ti] = fmaf(b[ri], a[ti], acc[ri][ti]);
        }
        __syncthreads();
    }

    // permuted epilogue: row tile lies entirely inside one (gate, rank) block
    const int gate = r0 >> 8;
    const int rank = (r0 >> 6) & 3;
    float* gout = g_gi + (size_t)dir * SEQ * G3 + rank * 192 + gate * 64;
#pragma unroll
    for (int ri = 0; ri < 4; ri++) {
        int rr = ty * 4 + ri;               // == row % 64
        float bias = B[r0 + rr];
#pragma unroll
        for (int ti = 0; ti < 4; ti++) {
            int s = t0 + tx * 4 + ti;
            gout[(size_t)s * G3 + rr] = acc[ri][ti] + bias;
        }
    }
}

// ---------------------------------------------------------------------------
// Kernel C: the recurrence. 2 clusters of 4 CTAs (one cluster per direction).
// CTA rank r owns h indices [64r, 64r+64) and gate rows {r*64+j, 256+r*64+j,
// 512+r*64+j}. Weights live in registers (64 f32x2 per thread).
// 384 threads = 12 warps: warp w -> half = w/6 (128-col half of h),
// local row = (w%6)*32 + lane (0..191).
// h exchange: DSMEM stores + one cluster-scope mbarrier (256 arrivals/step).
// ---------------------------------------------------------------------------
__global__ void __cluster_dims__(4, 1, 1) __launch_bounds__(384, 1)
gru_kernel(const float* __restrict__ whh1, const float* __restrict__ bhh1,
           const float* __restrict__ whh2, const float* __restrict__ bhh2,
           const float* __restrict__ h01, const float* __restrict__ h02,
           float* __restrict__ out) {
    __shared__ __align__(16) float hbuf[2][HID];   // double-buffered hidden state
    __shared__ float part[2][192];                 // per-half partial dots
    __shared__ __align__(8) ull mbar;

    const int tid  = threadIdx.x;
    const int dir  = blockIdx.y;
    const int rank = blockIdx.x;      // == cluster rank (cluster dims 4,1,1)
    const int w    = tid >> 5;
    const int lane = tid & 31;
    const int half = w / 6;                       // 0: cols 0..127, 1: cols 128..255
    const int rlocal = (w % 6) * 32 + lane;       // 0..191
    const int gate = rlocal >> 6;
    const int jrow = rlocal & 63;
    const int grow = gate * 256 + rank * 64 + jrow;

    const float* whh = dir ? whh2 : whh1;
    const float* bhh = dir ? bhh2 : bhh1;
    const float* h0  = dir ? h02  : h01;

    // ---- preload this thread's 128 weights as 64 f32x2 registers ----
    ull wreg[64];
    {
        const ull* wp = reinterpret_cast<const ull*>(whh + (size_t)grow * HID + half * 128);
#pragma unroll
        for (int i = 0; i < 64; i++) wreg[i] = __ldg(wp + i);
    }

    // ---- init ----
    if (tid < HID) hbuf[0][tid] = h0[tid];
    const unsigned mbar_a = s2u(&mbar);
    if (tid == 0) {
        asm volatile("mbarrier.init.shared.b64 [%0], %1;" :: "r"(mbar_a), "r"(256) : "memory");
    }
    float h_old = 0.f, br = 0.f, bz = 0.f, bn = 0.f;
    const float* gp = g_gi;
    if (tid < 64) {
        h_old = h0[rank * 64 + tid];
        br = bhh[rank * 64 + tid];
        bz = bhh[256 + rank * 64 + tid];
        bn = bhh[512 + rank * 64 + tid];
        gp = g_gi + (size_t)dir * SEQ * G3 + rank * 192 + tid;
    }
    __syncthreads();
    asm volatile("barrier.cluster.arrive.aligned;" ::: "memory");
    asm volatile("barrier.cluster.wait.aligned;" ::: "memory");

    const size_t hid_base = (size_t)SEQ * EMBD;                 // 819200
    const size_t fin_base = hid_base + (size_t)SEQ * 2 * HID;   // 2916352

    for (int t = 0; t < SEQ; t++) {
        const int s = dir ? (SEQ - 1 - t) : t;
        const int p = t & 1;

        // prefetch gi for this step (independent of h; overlaps the wait)
        float gir = 0.f, giz = 0.f, gin = 0.f;
        if (tid < 64) {
            const float* q = gp + (size_t)s * G3;
            gir = __ldg(q);
            giz = __ldg(q + 64);
            gin = __ldg(q + 128);
        }

        if (t > 0) {
            unsigned par = (unsigned)((t - 1) & 1);
            asm volatile(
                "{\n\t"
                ".reg .pred P;\n\t"
                "WL%=:\n\t"
                "mbarrier.try_wait.parity.acquire.cluster.shared::cta.b64 P, [%0], %1;\n\t"
                "@!P bra WL%=;\n\t"
                "}"
                :: "r"(mbar_a), "r"(par) : "memory");
        }

        // ---- matvec: 64 f32x2 FMAs, h via broadcast LDS.64 ----
        const ull* hb = reinterpret_cast<const ull*>(&hbuf[p][half * 128]);
        ull a0 = 0ull, a1 = 0ull;
#pragma unroll
        for (int i = 0; i < 64; i += 2) {
            a0 = fma2(wreg[i],     hb[i],     a0);
            a1 = fma2(wreg[i + 1], hb[i + 1], a1);
        }
        float sum;
        {
            float x0 = __uint_as_float((unsigned)a0);
            float x1 = __uint_as_float((unsigned)(a0 >> 32));
            float x2 = __uint_as_float((unsigned)a1);
            float x3 = __uint_as_float((unsigned)(a1 >> 32));
            sum = (x0 + x1) + (x2 + x3);
        }
        part[half][rlocal] = sum;
        __syncthreads();

        if (tid < 64) {
            const int j = tid;
            float ghr = part[0][j]       + part[1][j]       + br;
            float ghz = part[0][64 + j]  + part[1][64 + j]  + bz;
            float ghn = part[0][128 + j] + part[1][128 + j] + bn;
            float r = sigm(gir + ghr);
            float z = sigm(giz + ghz);
            float n = tanhx(gin + r * ghn);
            float hn = (1.0f - z) * n + z * h_old;
            h_old = hn;

            out[hid_base + (size_t)s * (2 * HID) + dir * HID + rank * 64 + j] = hn;
            if (t == SEQ - 1)
                out[fin_base + (size_t)dir * HID + rank * 64 + j] = hn;

            if (t < SEQ - 1) {
                unsigned dst = s2u(&hbuf[p ^ 1][rank * 64 + j]);
#pragma unroll
                for (int c = 0; c < 4; c++) {
                    unsigned ra;
                    asm volatile("mapa.shared::cluster.u32 %0, %1, %2;"
                                 : "=r"(ra) : "r"(dst), "r"(c));
                    asm volatile("st.shared::cluster.f32 [%0], %1;"
                                 :: "r"(ra), "f"(hn) : "memory");
                }
#pragma unroll
                for (int c = 0; c < 4; c++) {
                    unsigned rb;
                    asm volatile("mapa.shared::cluster.u32 %0, %1, %2;"
                                 : "=r"(rb) : "r"(mbar_a), "r"(c));
                    asm volatile(
                        "mbarrier.arrive.release.cluster.shared::cluster.b64 _, [%0];"
                        :: "r"(rb) : "memory");
                }
            }
        }
    }

    // no CTA may exit while peers could still touch its SMEM
    asm volatile("barrier.cluster.arrive.aligned;" ::: "memory");
    asm volatile("barrier.cluster.wait.aligned;" ::: "memory");
}

// ---------------------------------------------------------------------------
extern "C" void kernel_launch(void* const* d_in, const int* in_sizes, int n_in,
                              void* d_out, int out_size) {
    const int*   utt  = (const int*)  d_in[0];
    const float* h01  = (const float*)d_in[1];
    const float* h02  = (const float*)d_in[2];
    const float* embw = (const float*)d_in[3];
    const float* wih1 = (const float*)d_in[4];
    const float* whh1 = (const float*)d_in[5];
    const float* bih1 = (const float*)d_in[6];
    const float* bhh1 = (const float*)d_in[7];
    const float* wih2 = (const float*)d_in[8];
    const float* whh2 = (const float*)d_in[9];
    const float* bih2 = (const float*)d_in[10];
    const float* bhh2 = (const float*)d_in[11];
    float* out = (float*)d_out;

    embed_kernel<<<(SEQ * EMBD + 255) / 256, 256>>>(utt, embw, out);
    gi_gemm<<<dim3(64, 12, 2), 256>>>(out, wih1, bih1, wih2, bih2);
    gru_kernel<<<dim3(4, 2, 1), 384>>>(whh1, bhh1, whh2, bhh2, h01, h02, out);
}

// round 5
// speedup vs baseline: 1.2117x; 1.2117x over previous
#include <cuda_runtime.h>
#include <cstdint>

#define SEQ  4096
#define EMBD 200
#define HID  256
#define G3   768   // 3*HID
#define CL   4     // cluster size (CTAs per direction) -- proven launchable
#define ROWS 192   // gate rows per CTA = G3/CL
#define HCH  64    // hidden chunk per CTA = HID/CL

// Precomputed input-gate projections, permuted per (dir, t, rank):
// gi[dir*SEQ*G3 + s*G3 + rank*192 + gate*64 + j]
__device__ float g_gi[2u * SEQ * G3];

typedef unsigned long long ull;

__device__ __forceinline__ ull fma2(ull a, ull b, ull c) {
    ull d;
    asm("fma.rn.f32x2 %0, %1, %2, %3;" : "=l"(d) : "l"(a), "l"(b), "l"(c));
    return d;
}
__device__ __forceinline__ unsigned s2u(const void* p) {
    return (unsigned)__cvta_generic_to_shared(p);
}
__device__ __forceinline__ float sigm(float x) { return 1.0f / (1.0f + __expf(-x)); }
__device__ __forceinline__ float tanhx(float x) {
    float e = __expf(2.0f * x);
    return 1.0f - 2.0f / (e + 1.0f);
}

// ---------------------------------------------------------------------------
// Kernel A: embedding gather -> d_out[0 .. SEQ*EMBD)
// ---------------------------------------------------------------------------
__global__ void embed_kernel(const int* __restrict__ utt,
                             const float* __restrict__ embw,
                             float* __restrict__ out) {
    int i = blockIdx.x * blockDim.x + threadIdx.x;
    if (i < SEQ * EMBD) {
        int t = i / EMBD;
        int k = i - t * EMBD;
        out[i] = __ldg(&embw[(size_t)utt[t] * EMBD + k]);
    }
}

// ---------------------------------------------------------------------------
// Kernel B: gi = X @ W_ih^T + b_ih for both directions, written permuted.
// Grid (64, 12, 2): 64x64 tiles (t x rows), 256 threads, 4x4 micro-tile.
// (identical to the R2 kernel that passed)
// ---------------------------------------------------------------------------
__global__ void __launch_bounds__(256, 1)
gi_gemm(const float* __restrict__ X,
        const float* __restrict__ wih1, const float* __restrict__ bih1,
        const float* __restrict__ wih2, const float* __restrict__ bih2) {
    const int dir = blockIdx.z;
    const float* W = dir ? wih2 : wih1;
    const float* B = dir ? bih2 : bih1;
    const int t0 = blockIdx.x * 64;
    const int r0 = blockIdx.y * 64;

    __shared__ float xs[8][65];
    __shared__ float ws[8][65];

    const int tid = threadIdx.x;
    const int tx = tid & 15;      // t dimension
    const int ty = tid >> 4;      // row dimension

    float acc[4][4];
#pragma unroll
    for (int i = 0; i < 4; i++)
#pragma unroll
        for (int k = 0; k < 4; k++) acc[i][k] = 0.0f;

    for (int k0 = 0; k0 < EMBD; k0 += 8) {
#pragma unroll
        for (int i = 0; i < 2; i++) {
            int f = tid + i * 256;
            int kk = f & 7, tt = f >> 3;
            xs[kk][tt] = X[(size_t)(t0 + tt) * EMBD + k0 + kk];
        }
#pragma unroll
        for (int i = 0; i < 2; i++) {
            int f = tid + i * 256;
            int kk = f & 7, rr = f >> 3;
            ws[kk][rr] = W[(size_t)(r0 + rr) * EMBD + k0 + kk];
        }
        __syncthreads();
#pragma unroll
        for (int kk = 0; kk < 8; kk++) {
            float a[4], b[4];
#pragma unroll
            for (int i = 0; i < 4; i++) { a[i] = xs[kk][tx * 4 + i]; b[i] = ws[kk][ty * 4 + i]; }
#pragma unroll
            for (int ri = 0; ri < 4; ri++)
#pragma unroll
                for (int ti = 0; ti < 4; ti++)
                    acc[ri][ti] = fmaf(b[ri], a[ti], acc[ri][ti]);
        }
        __syncthreads();
    }

    // permuted epilogue: row -> (gate, rank, j) with 4-way rank split
#pragma unroll
    for (int ri = 0; ri < 4; ri++) {
        int row = r0 + ty * 4 + ri;
        int gate = row >> 8;
        int rk = (row >> 6) & 3;
        int jj = row & 63;
        float bias = B[row];
        float* gout = g_gi + (size_t)dir * SEQ * G3 + rk * ROWS + gate * 64 + jj;
#pragma unroll
        for (int ti = 0; ti < 4; ti++) {
            int s = t0 + tx * 4 + ti;
            gout[(size_t)s * G3] = acc[ri][ti] + bias;
        }
    }
}

// ---------------------------------------------------------------------------
// Kernel C: the recurrence. 2 clusters of 4 CTAs (one cluster per direction).
// CTA rank r owns h chunk [64r, 64r+64) and gate rows {g*256 + 64r + j}.
// 384 threads = 12 warps: warp w -> half = w/6 (128-col half of h),
// local row rl = (w%6)*32 + lane (0..191). Weights register-resident
// (64 f32x2 per thread).
// Exchange: weak DSMEM stores + per-thread cluster fence + named barrier
// over the 2 gate warps + 4 elected release-arrives (one per destination).
// ---------------------------------------------------------------------------
__global__ void __cluster_dims__(CL, 1, 1) __launch_bounds__(384, 1)
gru_kernel(const float* __restrict__ whh1, const float* __restrict__ bhh1,
           const float* __restrict__ whh2, const float* __restrict__ bhh2,
           const float* __restrict__ h01, const float* __restrict__ h02,
           float* __restrict__ out) {
    __shared__ __align__(16) float hbuf[2][HID];   // double-buffered hidden state
    __shared__ float part[2][ROWS];                // per-half partial dots
    __shared__ __align__(8) ull mbar;

    const int tid  = threadIdx.x;
    const int dir  = blockIdx.y;
    const int rank = blockIdx.x;      // == cluster rank (cluster dims CL,1,1)
    const int w    = tid >> 5;
    const int lane = tid & 31;
    const int half = w / 6;                        // 0: cols 0..127, 1: 128..255
    const int rl   = (w % 6) * 32 + lane;          // 0..191
    const int gate = rl >> 6;
    const int j    = rl & 63;
    const int grow = gate * 256 + rank * HCH + j;

    const float* whh = dir ? whh2 : whh1;
    const float* bhh = dir ? bhh2 : bhh1;
    const float* h0  = dir ? h02  : h01;

    // ---- preload this thread's 128 weights as 64 f32x2 registers ----
    ull wreg[64];
    {
        const ull* wp = reinterpret_cast<const ull*>(whh + (size_t)grow * HID + half * 128);
#pragma unroll
        for (int i = 0; i < 64; i++) wreg[i] = __ldg(wp + i);
    }

    // ---- init ----
    if (tid < HID) hbuf[0][tid] = h0[tid];
    const unsigned mbar_a = s2u(&mbar);
    if (tid == 0) {
        asm volatile("mbarrier.init.shared.b64 [%0], %1;" :: "r"(mbar_a), "r"(CL) : "memory");
    }

    // precompute remote SMEM addresses (loop-invariant)
    const unsigned hbase = s2u(hbuf);
    unsigned hb_remote[CL];
#pragma unroll
    for (int c = 0; c < CL; c++) {
        asm("mapa.shared::cluster.u32 %0, %1, %2;" : "=r"(hb_remote[c]) : "r"(hbase), "r"(c));
    }
    unsigned mb_remote = 0;
    if (tid < CL) {
        asm("mapa.shared::cluster.u32 %0, %1, %2;" : "=r"(mb_remote) : "r"(mbar_a), "r"(tid));
    }

    float h_old = 0.f, br = 0.f, bz = 0.f, bn = 0.f;
    const float* gp = g_gi;
    float* outp = out;
    if (tid < HCH) {
        h_old = h0[rank * HCH + tid];
        br = bhh[rank * HCH + tid];
        bz = bhh[256 + rank * HCH + tid];
        bn = bhh[512 + rank * HCH + tid];
        gp = g_gi + (size_t)dir * SEQ * G3 + rank * ROWS + tid;
        outp = out + (size_t)SEQ * EMBD + dir * HID + rank * HCH + tid;
    }
    __syncthreads();
    asm volatile("barrier.cluster.arrive.aligned;" ::: "memory");
    asm volatile("barrier.cluster.wait.aligned;" ::: "memory");

    const size_t fin_base = (size_t)SEQ * EMBD + (size_t)SEQ * 2 * HID;

    for (int t = 0; t < SEQ; t++) {
        const int s = dir ? (SEQ - 1 - t) : t;
        const int p = t & 1;

        // prefetch gi (independent of h; overlaps the wait)
        float gir = 0.f, giz = 0.f, gin = 0.f;
        if (tid < HCH) {
            const float* qq = gp + (size_t)s * G3;
            gir = __ldg(qq);
            giz = __ldg(qq + 64);
            gin = __ldg(qq + 128);
        }

        if (t > 0) {
            unsigned par = (unsigned)((t - 1) & 1);
            asm volatile(
                "{\n\t"
                ".reg .pred P;\n\t"
                "WL%=:\n\t"
                "mbarrier.try_wait.parity.acquire.cluster.shared::cta.b64 P, [%0], %1;\n\t"
                "@!P bra WL%=;\n\t"
                "}"
                :: "r"(mbar_a), "r"(par) : "memory");
        }

        // ---- matvec: 64 f32x2 FMAs, h via broadcast LDS.128 ----
        const ulonglong2* hb = reinterpret_cast<const ulonglong2*>(&hbuf[p][half * 128]);
        ull a0 = 0ull, a1 = 0ull;
#pragma unroll
        for (int i = 0; i < 32; i++) {
            ulonglong2 hv = hb[i];
            a0 = fma2(wreg[2 * i],     hv.x, a0);
            a1 = fma2(wreg[2 * i + 1], hv.y, a1);
        }
        float sum;
        {
            float x0 = __uint_as_float((unsigned)a0);
            float x1 = __uint_as_float((unsigned)(a0 >> 32));
            float x2 = __uint_as_float((unsigned)a1);
            float x3 = __uint_as_float((unsigned)(a1 >> 32));
            sum = (x0 + x1) + (x2 + x3);
        }
        part[half][rl] = sum;
        __syncthreads();

        if (tid < HCH) {
            float ghr = part[0][tid]       + part[1][tid]       + br;
            float ghz = part[0][64 + tid]  + part[1][64 + tid]  + bz;
            float ghn = part[0][128 + tid] + part[1][128 + tid] + bn;
            float r = sigm(gir + ghr);
            float z = sigm(giz + ghz);
            float n = tanhx(gin + r * ghn);
            float hn = (1.0f - z) * n + z * h_old;
            h_old = hn;

            outp[(size_t)s * (2 * HID)] = hn;
            if (t == SEQ - 1)
                out[fin_base + (size_t)dir * HID + rank * HCH + tid] = hn;

            if (t < SEQ - 1) {
                unsigned off = (unsigned)((p ^ 1) * (HID * 4) + (rank * HCH + tid) * 4);
#pragma unroll
                for (int c = 0; c < CL; c++) {
                    asm volatile("st.shared::cluster.f32 [%0], %1;"
                                 :: "r"(hb_remote[c] + off), "f"(hn) : "memory");
                }
                // release-order this thread's cluster stores, then let the
                // elected lanes publish on behalf of both gate warps
                asm volatile("fence.acq_rel.cluster;" ::: "memory");
                asm volatile("bar.sync 1, 64;" ::: "memory");
                if (tid < CL) {
                    asm volatile(
                        "mbarrier.arrive.release.cluster.shared::cluster.b64 _, [%0];"
                        :: "r"(mb_remote) : "memory");
                }
            }
        }
    }

    // no CTA may exit while peers could still touch its SMEM
    asm volatile("barrier.cluster.arrive.aligned;" ::: "memory");
    asm volatile("barrier.cluster.wait.aligned;" ::: "memory");
}

// ---------------------------------------------------------------------------
extern "C" void kernel_launch(void* const* d_in, const int* in_sizes, int n_in,
                              void* d_out, int out_size) {
    const int*   utt  = (const int*)  d_in[0];
    const float* h01  = (const float*)d_in[1];
    const float* h02  = (const float*)d_in[2];
    const float* embw = (const float*)d_in[3];
    const float* wih1 = (const float*)d_in[4];
    const float* whh1 = (const float*)d_in[5];
    const float* bih1 = (const float*)d_in[6];
    const float* bhh1 = (const float*)d_in[7];
    const float* wih2 = (const float*)d_in[8];
    const float* whh2 = (const float*)d_in[9];
    const float* bih2 = (const float*)d_in[10];
    const float* bhh2 = (const float*)d_in[11];
    float* out = (float*)d_out;

    embed_kernel<<<(SEQ * EMBD + 255) / 256, 256>>>(utt, embw, out);
    gi_gemm<<<dim3(64, 12, 2), 256>>>(out, wih1, bih1, wih2, bih2);
    gru_kernel<<<dim3(CL, 2, 1), 384>>>(whh1, bhh1, whh2, bhh2, h01, h02, out);
}

// round 7
// speedup vs baseline: 1.9715x; 1.6271x over previous
#include <cuda_runtime.h>
#include <cstdint>

#define SEQ  4096
#define EMBD 200
#define HID  256
#define G3   768   // 3*HID
#define CL   4     // cluster size (CTAs per direction)
#define ROWS 192   // gate rows per CTA = G3/CL
#define HCH  64    // hidden chunk per CTA = HID/CL
#define TXB  (CL * HCH * 4)   // 1024 bytes of h delivered to each CTA per step

// Precomputed input-gate projections, permuted per (dir, t, rank):
// gi[dir*SEQ*G3 + s*G3 + rank*192 + gate*64 + j]
__device__ float g_gi[2u * SEQ * G3];

typedef unsigned long long ull;

__device__ __forceinline__ ull fma2(ull a, ull b, ull c) {
    ull d;
    asm("fma.rn.f32x2 %0, %1, %2, %3;" : "=l"(d) : "l"(a), "l"(b), "l"(c));
    return d;
}
__device__ __forceinline__ unsigned s2u(const void* p) {
    return (unsigned)__cvta_generic_to_shared(p);
}
__device__ __forceinline__ float sigm(float x) { return 1.0f / (1.0f + __expf(-x)); }
__device__ __forceinline__ float tanhx(float x) {
    float e = __expf(2.0f * x);
    return 1.0f - 2.0f / (e + 1.0f);
}

// ---------------------------------------------------------------------------
// Kernel A: embedding gather -> d_out[0 .. SEQ*EMBD)
// ---------------------------------------------------------------------------
__global__ void embed_kernel(const int* __restrict__ utt,
                             const float* __restrict__ embw,
                             float* __restrict__ out) {
    int i = blockIdx.x * blockDim.x + threadIdx.x;
    if (i < SEQ * EMBD) {
        int t = i / EMBD;
        int k = i - t * EMBD;
        out[i] = __ldg(&embw[(size_t)utt[t] * EMBD + k]);
    }
}

// ---------------------------------------------------------------------------
// Kernel B: gi = X @ W_ih^T + b_ih for both directions, written permuted.
// Grid (64, 12, 2): 64x64 tiles (t x rows), 256 threads, 4x4 micro-tile.
// ---------------------------------------------------------------------------
__global__ void __launch_bounds__(256, 1)
gi_gemm(const float* __restrict__ X,
        const float* __restrict__ wih1, const float* __restrict__ bih1,
        const float* __restrict__ wih2, const float* __restrict__ bih2) {
    const int dir = blockIdx.z;
    const float* W = dir ? wih2 : wih1;
    const float* B = dir ? bih2 : bih1;
    const int t0 = blockIdx.x * 64;
    const int r0 = blockIdx.y * 64;

    __shared__ float xs[8][65];
    __shared__ float ws[8][65];

    const int tid = threadIdx.x;
    const int tx = tid & 15;      // t dimension
    const int ty = tid >> 4;      // row dimension

    float acc[4][4];
#pragma unroll
    for (int i = 0; i < 4; i++)
#pragma unroll
        for (int k = 0; k < 4; k++) acc[i][k] = 0.0f;

    for (int k0 = 0; k0 < EMBD; k0 += 8) {
#pragma unroll
        for (int i = 0; i < 2; i++) {
            int f = tid + i * 256;
            int kk = f & 7, tt = f >> 3;
            xs[kk][tt] = X[(size_t)(t0 + tt) * EMBD + k0 + kk];
        }
#pragma unroll
        for (int i = 0; i < 2; i++) {
            int f = tid + i * 256;
            int kk = f & 7, rr = f >> 3;
            ws[kk][rr] = W[(size_t)(r0 + rr) * EMBD + k0 + kk];
        }
        __syncthreads();
#pragma unroll
        for (int kk = 0; kk < 8; kk++) {
            float a[4], b[4];
#pragma unroll
            for (int i = 0; i < 4; i++) { a[i] = xs[kk][tx * 4 + i]; b[i] = ws[kk][ty * 4 + i]; }
#pragma unroll
            for (int ri = 0; ri < 4; ri++)
#pragma unroll
                for (int ti = 0; ti < 4; ti++)
                    acc[ri][ti] = fmaf(b[ri], a[ti], acc[ri][ti]);
        }
        __syncthreads();
    }

    // permuted epilogue: row -> (gate, rank, j) with 4-way rank split
#pragma unroll
    for (int ri = 0; ri < 4; ri++) {
        int row = r0 + ty * 4 + ri;
        int gate = row >> 8;
        int rk = (row >> 6) & 3;
        int jj = row & 63;
        float bias = B[row];
        float* gout = g_gi + (size_t)dir * SEQ * G3 + rk * ROWS + gate * 64 + jj;
#pragma unroll
        for (int ti = 0; ti < 4; ti++) {
            int s = t0 + tx * 4 + ti;
            gout[(size_t)s * G3] = acc[ri][ti] + bias;
        }
    }
}

// ---------------------------------------------------------------------------
// Kernel C: the recurrence. 2 clusters of 4 CTAs (one cluster per direction).
// CTA rank r owns h chunk [64r, 64r+64) and gate rows {g*256 + 64r + j}.
// 384 threads = 12 warps: warp w -> half = w/6, local row rl = (w%6)*32+lane.
// Weights register-resident (64 f32x2 per thread).
// Exchange: st.async.shared::cluster with mbarrier complete_tx — the store
// itself signals the destination CTA's ping/pong tx-barrier. No fence, no
// named barrier, no separate arrive on the critical path.
// ---------------------------------------------------------------------------
__global__ void __cluster_dims__(CL, 1, 1) __launch_bounds__(384, 1)
gru_kernel(const float* __restrict__ whh1, const float* __restrict__ bhh1,
           const float* __restrict__ whh2, const float* __restrict__ bhh2,
           const float* __restrict__ h01, const float* __restrict__ h02,
           float* __restrict__ out) {
    __shared__ __align__(16) float hbuf[2][HID];   // double-buffered hidden state
    __shared__ float part[2][ROWS];                // per-half partial dots
    __shared__ __align__(8) ull mbar[2];           // ping/pong tx barriers

    const int tid  = threadIdx.x;
    const int dir  = blockIdx.y;
    const int rank = blockIdx.x;      // == cluster rank (cluster dims CL,1,1)
    const int w    = tid >> 5;
    const int lane = tid & 31;
    const int half = w / 6;                        // 0: cols 0..127, 1: 128..255
    const int rl   = (w % 6) * 32 + lane;          // 0..191
    const int gate = rl >> 6;
    const int j    = rl & 63;
    const int grow = gate * 256 + rank * HCH + j;

    const float* whh = dir ? whh2 : whh1;
    const float* bhh = dir ? bhh2 : bhh1;
    const float* h0  = dir ? h02  : h01;

    // ---- preload this thread's 128 weights as 64 f32x2 registers ----
    ull wreg[64];
    {
        const ull* wp = reinterpret_cast<const ull*>(whh + (size_t)grow * HID + half * 128);
#pragma unroll
        for (int i = 0; i < 64; i++) wreg[i] = __ldg(wp + i);
    }

    // ---- init ----
    if (tid < HID) hbuf[0][tid] = h0[tid];
    const unsigned mbar_a = s2u(mbar);             // base of mbar[0]; mbar[1] at +8
    if (tid == 0) {
        asm volatile("mbarrier.init.shared.b64 [%0], %1;" :: "r"(mbar_a),     "r"(1) : "memory");
        asm volatile("mbarrier.init.shared.b64 [%0], %1;" :: "r"(mbar_a + 8), "r"(1) : "memory");
        // pre-arm phase 0 of both barriers (covers exchanges t=0 and t=1)
        asm volatile("mbarrier.arrive.expect_tx.shared.b64 _, [%0], %1;"
                     :: "r"(mbar_a), "r"(TXB) : "memory");
        asm volatile("mbarrier.arrive.expect_tx.shared.b64 _, [%0], %1;"
                     :: "r"(mbar_a + 8), "r"(TXB) : "memory");
    }

    // precompute remote SMEM addresses (loop-invariant)
    const unsigned hbase = s2u(hbuf);
    unsigned hb_remote[CL], mb_remote[CL];
#pragma unroll
    for (int c = 0; c < CL; c++) {
        asm("mapa.shared::cluster.u32 %0, %1, %2;" : "=r"(hb_remote[c]) : "r"(hbase), "r"(c));
        asm("mapa.shared::cluster.u32 %0, %1, %2;" : "=r"(mb_remote[c]) : "r"(mbar_a), "r"(c));
    }

    float h_old = 0.f, br = 0.f, bz = 0.f, bn = 0.f;
    const float* gp = g_gi;
    float* outp = out;
    if (tid < HCH) {
        h_old = h0[rank * HCH + tid];
        br = bhh[rank * HCH + tid];
        bz = bhh[256 + rank * HCH + tid];
        bn = bhh[512 + rank * HCH + tid];
        gp = g_gi + (size_t)dir * SEQ * G3 + rank * ROWS + tid;
        outp = out + (size_t)SEQ * EMBD + dir * HID + rank * HCH + tid;
    }
    __syncthreads();
    // all CTAs' mbarrier init + pre-arm must be visible before any st.async
    asm volatile("barrier.cluster.arrive.aligned;" ::: "memory");
    asm volatile("barrier.cluster.wait.aligned;" ::: "memory");

    const size_t fin_base = (size_t)SEQ * EMBD + (size_t)SEQ * 2 * HID;

    for (int t = 0; t < SEQ; t++) {
        const int s = dir ? (SEQ - 1 - t) : t;
        const int p = t & 1;

        // prefetch gi (independent of h; overlaps the wait)
        float gir = 0.f, giz = 0.f, gin = 0.f;
        if (tid < HCH) {
            const float* qq = gp + (size_t)s * G3;
            gir = __ldg(qq);
            giz = __ldg(qq + 64);
            gin = __ldg(qq + 128);
        }

        if (t > 0) {
            const unsigned mb = mbar_a + (unsigned)(((t - 1) & 1) << 3);
            const unsigned par = (unsigned)(((t - 1) >> 1) & 1);
            asm volatile(
                "{\n\t"
                ".reg .pred P;\n\t"
                "WL%=:\n\t"
                "mbarrier.try_wait.parity.acquire.cluster.shared::cta.b64 P, [%0], %1;\n\t"
                "@!P bra WL%=;\n\t"
                "}"
                :: "r"(mb), "r"(par) : "memory");
            // re-arm this barrier for its next phase (used by exchange t+1).
            // Ordered before this CTA's step-t st.async deliveries by the
            // __syncthreads below; any producer of the next phase causally
            // depends on those deliveries, so the re-arm always lands first.
            if (tid == 64) {
                asm volatile("mbarrier.arrive.expect_tx.shared.b64 _, [%0], %1;"
                             :: "r"(mb), "r"(TXB) : "memory");
            }
        }

        // ---- matvec: 64 f32x2 FMAs, h via broadcast LDS.128 ----
        const ulonglong2* hb = reinterpret_cast<const ulonglong2*>(&hbuf[p][half * 128]);
        ull a0 = 0ull, a1 = 0ull;
#pragma unroll
        for (int i = 0; i < 32; i++) {
            ulonglong2 hv = hb[i];
            a0 = fma2(wreg[2 * i],     hv.x, a0);
            a1 = fma2(wreg[2 * i + 1], hv.y, a1);
        }
        float sum;
        {
            float x0 = __uint_as_float((unsigned)a0);
            float x1 = __uint_as_float((unsigned)(a0 >> 32));
            float x2 = __uint_as_float((unsigned)a1);
            float x3 = __uint_as_float((unsigned)(a1 >> 32));
            sum = (x0 + x1) + (x2 + x3);
        }
        part[half][rl] = sum;
        __syncthreads();

        if (tid < HCH) {
            float ghr = part[0][tid]       + part[1][tid]       + br;
            float ghz = part[0][64 + tid]  + part[1][64 + tid]  + bz;
            float ghn = part[0][128 + tid] + part[1][128 + tid] + bn;
            float r = sigm(gir + ghr);
            float z = sigm(giz + ghz);
            float n = tanhx(gin + r * ghn);
            float hn = (1.0f - z) * n + z * h_old;
            h_old = hn;

            if (t < SEQ - 1) {
                // single-hop exchange: store + completion signal in one op
                const unsigned off = (unsigned)((p ^ 1) * (HID * 4) + (rank * HCH + tid) * 4);
                const unsigned mboff = (unsigned)(p << 3);
                const unsigned hv = __float_as_uint(hn);
#pragma unroll
                for (int c = 0; c < CL; c++) {
                    asm volatile(
                        "st.async.shared::cluster.mbarrier::complete_tx::bytes.u32 "
                        "[%0], %1, [%2];"
                        :: "r"(hb_remote[c] + off), "r"(hv), "r"(mb_remote[c] + mboff)
                        : "memory");
                }
            }

            // off the critical path
            outp[(size_t)s * (2 * HID)] = hn;
            if (t == SEQ - 1)
                out[fin_base + (size_t)dir * HID + rank * HCH + tid] = hn;
        }
    }

    // no CTA may exit while peers could still touch its SMEM
    asm volatile("barrier.cluster.arrive.aligned;" ::: "memory");
    asm volatile("barrier.cluster.wait.aligned;" ::: "memory");
}

// ---------------------------------------------------------------------------
extern "C" void kernel_launch(void* const* d_in, const int* in_sizes, int n_in,
                              void* d_out, int out_size) {
    const int*   utt  = (const int*)  d_in[0];
    const float* h01  = (const float*)d_in[1];
    const float* h02  = (const float*)d_in[2];
    const float* embw = (const float*)d_in[3];
    const float* wih1 = (const float*)d_in[4];
    const float* whh1 = (const float*)d_in[5];
    const float* bih1 = (const float*)d_in[6];
    const float* bhh1 = (const float*)d_in[7];
    const float* wih2 = (const float*)d_in[8];
    const float* whh2 = (const float*)d_in[9];
    const float* bih2 = (const float*)d_in[10];
    const float* bhh2 = (const float*)d_in[11];
    float* out = (float*)d_out;

    embed_kernel<<<(SEQ * EMBD + 255) / 256, 256>>>(utt, embw, out);
    gi_gemm<<<dim3(64, 12, 2), 256>>>(out, wih1, bih1, wih2, bih2);
    gru_kernel<<<dim3(CL, 2, 1), 384>>>(whh1, bhh1, whh2, bhh2, h01, h02, out);
}